// round 4
// baseline (speedup 1.0000x reference)
#include <cuda_runtime.h>
#include <math.h>

// Problem constants
#define BZ   8
#define DI   256
#define DS   512
#define DO   256
#define LL   4096
#define NCH  32          // scan chunks
#define CLEN 128         // LL / NCH  (power of two: A^CLEN via 7 squarings)
#define LANES (BZ*DS)    // 4096

// Scratch: 64MB Bu / x buffer in (l, b, s) layout, plus chunk stitch buffers.
__device__ float g_Bu[(size_t)LL * BZ * DS];
__device__ float g_last[NCH * LANES];
__device__ float g_carry[NCH * LANES];

__device__ __forceinline__ float softplus_f(float x) {
    return fmaxf(x, 0.f) + log1pf(expf(-fabsf(x)));
}

// ---------------------------------------------------------------------------
// GEMM1: g_Bu[l][b][s] = sum_i u[b][i][l] * Bm[s][i]
// Tiles: 64(l) x 64(s), K-tile 16. 256 threads, 4x4 micro-tile per thread.
// ---------------------------------------------------------------------------
__global__ __launch_bounds__(256) void gemm1_kernel(const float* __restrict__ u,
                                                    const float* __restrict__ Bm) {
    __shared__ float Au[16][64];   // [k][l]
    __shared__ float Bs[16][68];   // [k][s], padded

    const int l0 = blockIdx.x * 64;
    const int s0 = blockIdx.y * 64;
    const int b  = blockIdx.z;
    const int tid = threadIdx.x;
    const int tx = tid & 15;       // s fragment
    const int ty = tid >> 4;       // l fragment

    // u-tile load mapping: k = tid>>4, 4 consecutive l
    const int uk  = tid >> 4;
    const int ul4 = (tid & 15) * 4;
    // B-tile (transposed) load mapping: s = tid>>2, 4 consecutive k
    const int bsr = tid >> 2;
    const int bk  = (tid & 3) * 4;

    const float* uBase = u + ((size_t)b * DI) * LL + l0 + ul4;
    const float* bBase = Bm + (size_t)(s0 + bsr) * DI + bk;

    float acc[4][4] = {};

    for (int k0 = 0; k0 < DI; k0 += 16) {
        float4 a4 = *(const float4*)(uBase + (size_t)(k0 + uk) * LL);
        *(float4*)&Au[uk][ul4] = a4;

        float4 b4 = *(const float4*)(bBase + k0);
        Bs[bk + 0][bsr] = b4.x;
        Bs[bk + 1][bsr] = b4.y;
        Bs[bk + 2][bsr] = b4.z;
        Bs[bk + 3][bsr] = b4.w;
        __syncthreads();

        #pragma unroll
        for (int k = 0; k < 16; k++) {
            float4 av = *(const float4*)&Au[k][ty * 4];
            float4 bv = *(const float4*)&Bs[k][tx * 4];
            float ar[4] = {av.x, av.y, av.z, av.w};
            float br[4] = {bv.x, bv.y, bv.z, bv.w};
            #pragma unroll
            for (int i = 0; i < 4; i++)
                #pragma unroll
                for (int j = 0; j < 4; j++)
                    acc[i][j] = fmaf(ar[i], br[j], acc[i][j]);
        }
        __syncthreads();
    }

    #pragma unroll
    for (int i = 0; i < 4; i++) {
        int l = l0 + ty * 4 + i;
        float4 v = make_float4(acc[i][0], acc[i][1], acc[i][2], acc[i][3]);
        *(float4*)(g_Bu + ((size_t)l * BZ + b) * DS + s0 + tx * 4) = v;
    }
}

// ---------------------------------------------------------------------------
// Scan phase A: per (chunk, b, s): local scan from 0 over CLEN steps,
// record ONLY the last value (read-only pass over g_Bu).
// Thread mapping t = c*LANES + b*DS + s  (s fastest -> coalesced).
// ---------------------------------------------------------------------------
__global__ __launch_bounds__(256) void scanA_kernel(const float* __restrict__ Aun) {
    const int t    = blockIdx.x * 256 + threadIdx.x;
    const int lane = t & (LANES - 1);
    const int c    = t >> 12;                 // LANES = 4096 = 2^12
    const int s    = lane & (DS - 1);

    const float A = -softplus_f(Aun[s]);
    const float* g = g_Bu + (size_t)(c * CLEN) * LANES + lane;

    float x = 0.f;
    #pragma unroll 8
    for (int j = 0; j < CLEN; j++) {
        x = fmaf(A, x, g[(size_t)j * LANES]);
    }
    g_last[t] = x;
}

// ---------------------------------------------------------------------------
// Scan phase B: per (b, s) lane: stitch 32 chunk carries.
// carry[c] = state x_{c*CLEN - 1};  carry[0] = h0;  S_{c+1} = A^CLEN*S_c + last_c
// ---------------------------------------------------------------------------
__global__ __launch_bounds__(256) void scanB_kernel(const float* __restrict__ Aun,
                                                    const float* __restrict__ h0) {
    const int lane = blockIdx.x * 256 + threadIdx.x;   // 0..LANES-1
    const int s = lane & (DS - 1);

    const float A = -softplus_f(Aun[s]);
    float Ap = A;
    #pragma unroll
    for (int i = 0; i < 7; i++) Ap *= Ap;              // A^128 (CLEN=2^7)

    float h = h0[s];
    #pragma unroll
    for (int c = 0; c < NCH; c++) {
        g_carry[c * LANES + lane] = h;
        h = fmaf(Ap, h, g_last[c * LANES + lane]);
    }
}

// ---------------------------------------------------------------------------
// Scan phase C: full re-scan of each chunk with the correct carry init,
// write x in place over g_Bu.
// ---------------------------------------------------------------------------
__global__ __launch_bounds__(256) void scanC_kernel(const float* __restrict__ Aun) {
    const int t    = blockIdx.x * 256 + threadIdx.x;
    const int lane = t & (LANES - 1);
    const int c    = t >> 12;
    const int s    = lane & (DS - 1);

    const float A = -softplus_f(Aun[s]);
    float x = g_carry[t];                              // x_{c*CLEN - 1}
    float* g = g_Bu + (size_t)(c * CLEN) * LANES + lane;

    #pragma unroll 4
    for (int j = 0; j < CLEN; j++) {
        float v = g[(size_t)j * LANES];
        x = fmaf(A, x, v);
        g[(size_t)j * LANES] = x;
    }
}

// ---------------------------------------------------------------------------
// GEMM2: Y[b][o][l] = sum_s Cm[o][s]*x[l][b][s] + sum_i Dm[o][i]*u[b][i][l]
// Tiles: 64(o) x 64(l), K over DS then DI. 256 threads, 4x4 micro-tile.
// ---------------------------------------------------------------------------
__global__ __launch_bounds__(256) void gemm2_kernel(const float* __restrict__ u,
                                                    const float* __restrict__ Cm,
                                                    const float* __restrict__ Dm,
                                                    float* __restrict__ Y) {
    __shared__ float Ws[16][68];   // [k][o], padded (transposed weight)
    __shared__ float Xs[16][68];   // [k][l], padded

    const int l0 = blockIdx.x * 64;
    const int o0 = blockIdx.y * 64;
    const int b  = blockIdx.z;
    const int tid = threadIdx.x;
    const int tx = tid & 15;       // l fragment
    const int ty = tid >> 4;       // o fragment

    // transposed-load mapping (weights and x): row = tid>>2, 4 consecutive k
    const int wr = tid >> 2;
    const int wk = (tid & 3) * 4;
    // direct-load mapping for u: k = tid>>4, 4 consecutive l
    const int uk  = tid >> 4;
    const int ul4 = (tid & 15) * 4;

    float acc[4][4] = {};

    // ---- Phase 1: K over DS, activation = x (g_Bu), weight = C ----
    {
        const float* cBase = Cm + (size_t)(o0 + wr) * DS + wk;
        const float* xBase = g_Bu + ((size_t)(l0 + wr) * BZ + b) * DS + wk;
        for (int k0 = 0; k0 < DS; k0 += 16) {
            float4 w4 = *(const float4*)(cBase + k0);
            Ws[wk + 0][wr] = w4.x;
            Ws[wk + 1][wr] = w4.y;
            Ws[wk + 2][wr] = w4.z;
            Ws[wk + 3][wr] = w4.w;

            float4 x4 = *(const float4*)(xBase + k0);
            Xs[wk + 0][wr] = x4.x;
            Xs[wk + 1][wr] = x4.y;
            Xs[wk + 2][wr] = x4.z;
            Xs[wk + 3][wr] = x4.w;
            __syncthreads();

            #pragma unroll
            for (int k = 0; k < 16; k++) {
                float4 wv = *(const float4*)&Ws[k][ty * 4];
                float4 xv = *(const float4*)&Xs[k][tx * 4];
                float wrg[4] = {wv.x, wv.y, wv.z, wv.w};
                float xrg[4] = {xv.x, xv.y, xv.z, xv.w};
                #pragma unroll
                for (int i = 0; i < 4; i++)
                    #pragma unroll
                    for (int j = 0; j < 4; j++)
                        acc[i][j] = fmaf(wrg[i], xrg[j], acc[i][j]);
            }
            __syncthreads();
        }
    }

    // ---- Phase 2: K over DI, activation = u (direct), weight = D ----
    {
        const float* dBase = Dm + (size_t)(o0 + wr) * DI + wk;
        const float* uBase = u + ((size_t)b * DI) * LL + l0 + ul4;
        for (int k0 = 0; k0 < DI; k0 += 16) {
            float4 w4 = *(const float4*)(dBase + k0);
            Ws[wk + 0][wr] = w4.x;
            Ws[wk + 1][wr] = w4.y;
            Ws[wk + 2][wr] = w4.z;
            Ws[wk + 3][wr] = w4.w;

            float4 a4 = *(const float4*)(uBase + (size_t)(k0 + uk) * LL);
            *(float4*)&Xs[uk][ul4] = a4;
            __syncthreads();

            #pragma unroll
            for (int k = 0; k < 16; k++) {
                float4 wv = *(const float4*)&Ws[k][ty * 4];
                float4 xv = *(const float4*)&Xs[k][tx * 4];
                float wrg[4] = {wv.x, wv.y, wv.z, wv.w};
                float xrg[4] = {xv.x, xv.y, xv.z, xv.w};
                #pragma unroll
                for (int i = 0; i < 4; i++)
                    #pragma unroll
                    for (int j = 0; j < 4; j++)
                        acc[i][j] = fmaf(wrg[i], xrg[j], acc[i][j]);
            }
            __syncthreads();
        }
    }

    #pragma unroll
    for (int i = 0; i < 4; i++) {
        int o = o0 + ty * 4 + i;
        float4 v = make_float4(acc[i][0], acc[i][1], acc[i][2], acc[i][3]);
        *(float4*)(Y + ((size_t)b * DO + o) * LL + l0 + tx * 4) = v;
    }
}

// ---------------------------------------------------------------------------
// Launch. Inputs (metadata order): u, A_unconstrained, B_mat, C_mat, D_mat, h0
// ---------------------------------------------------------------------------
extern "C" void kernel_launch(void* const* d_in, const int* in_sizes, int n_in,
                              void* d_out, int out_size) {
    const float* u   = (const float*)d_in[0];
    const float* Aun = (const float*)d_in[1];
    const float* Bm  = (const float*)d_in[2];
    const float* Cm  = (const float*)d_in[3];
    const float* Dm  = (const float*)d_in[4];
    const float* h0  = (const float*)d_in[5];
    float* Y = (float*)d_out;

    dim3 g1(LL / 64, DS / 64, BZ);
    gemm1_kernel<<<g1, 256>>>(u, Bm);

    scanA_kernel<<<(NCH * LANES) / 256, 256>>>(Aun);
    scanB_kernel<<<LANES / 256, 256>>>(Aun, h0);
    scanC_kernel<<<(NCH * LANES) / 256, 256>>>(Aun);

    dim3 g2(LL / 64, DO / 64, BZ);
    gemm2_kernel<<<g2, 256>>>(u, Cm, Dm, Y);
}

// round 6
// speedup vs baseline: 1.0784x; 1.0784x over previous
#include <cuda_runtime.h>
#include <cuda_bf16.h>
#include <mma.h>
#include <cstdint>
#include <math.h>

using namespace nvcuda;

// Problem constants
#define BZ   8
#define DI   256
#define DS   512
#define DO   256
#define LL   4096
#define NCH  32
#define CLEN 128
#define LANES (BZ*DS)

// ---------------- scratch ----------------
__device__ float g_Bu[(size_t)LL * BZ * DS];     // (l, b, s) fp32
__device__ float g_last[NCH * LANES];
__device__ float g_carry[NCH * LANES];

// split weights (bf16 hi/lo), layouts identical to fp32 originals (row-major [n][k])
#define WB_OFF 0
#define WC_OFF (512*256)
#define WD_OFF (WC_OFF + 256*512)
#define WTOT   (WD_OFF + 256*256)
__device__ __nv_bfloat16 g_whi[WTOT];
__device__ __nv_bfloat16 g_wlo[WTOT];

__device__ __forceinline__ float softplus_f(float x) {
    return fmaxf(x, 0.f) + log1pf(expf(-fabsf(x)));
}

__device__ __forceinline__ void split2(float x, float y, uint32_t& hi, uint32_t& lo) {
    __nv_bfloat16 hx = __float2bfloat16(x);
    __nv_bfloat16 hy = __float2bfloat16(y);
    __nv_bfloat16 lx = __float2bfloat16(x - __bfloat162float(hx));
    __nv_bfloat16 ly = __float2bfloat16(y - __bfloat162float(hy));
    __nv_bfloat162 h; h.x = hx; h.y = hy;
    __nv_bfloat162 l; l.x = lx; l.y = ly;
    hi = *(uint32_t*)&h; lo = *(uint32_t*)&l;
}

// ---------------- weight split prep ----------------
__global__ void prep_kernel(const float* __restrict__ Bm, const float* __restrict__ Cm,
                            const float* __restrict__ Dm) {
    int i = blockIdx.x * 256 + threadIdx.x;
    if (i >= WTOT) return;
    float v = (i < WC_OFF) ? Bm[i] : (i < WD_OFF ? Cm[i - WC_OFF] : Dm[i - WD_OFF]);
    __nv_bfloat16 h = __float2bfloat16(v);
    g_whi[i] = h;
    g_wlo[i] = __float2bfloat16(v - __bfloat162float(h));
}

// ---------------- SMEM layout (both GEMMs) ----------------
// A hi/lo regions: 18432 B each (fits [64][136] col-major or [128][72] row-major bf16)
// stage: 36864 B fp32 (fits [64][129] u-stage or [128][72] epilogue)
#define OFF_AHI 0
#define OFF_ALO 18432
#define OFF_STG 36864
#define SMEM_BYTES (36864 + 36864)
#define LDA_COL 136   // col-major A: [k][m], ldm in elements
#define LDA_ROW 72    // row-major A: [m][k]

// Stage-transpose a 64(k=i) x 128(l) tile of u (l-contiguous) into
// col-major bf16 hi/lo A tiles: Ahi[k*136 + m].
__device__ __forceinline__ void fill_A_from_u(char* smem, const float* __restrict__ u,
                                              int b, int k0, int l0, int tid) {
    float* st = (float*)(smem + OFF_STG);       // [64][129]
    {
        const int i = tid >> 2;                 // 0..63
        const int lseg = (tid & 3) * 32;
        const float* up = u + ((size_t)b * DI + k0 + i) * LL + l0 + lseg;
        float* sp = st + i * 129 + lseg;
        #pragma unroll
        for (int q = 0; q < 8; q++) {
            float4 v = *(const float4*)(up + q * 4);
            sp[q * 4 + 0] = v.x; sp[q * 4 + 1] = v.y;
            sp[q * 4 + 2] = v.z; sp[q * 4 + 3] = v.w;
        }
    }
    __syncthreads();
    {
        __nv_bfloat16* Ahi = (__nv_bfloat16*)(smem + OFF_AHI);
        __nv_bfloat16* Alo = (__nv_bfloat16*)(smem + OFF_ALO);
        const int k = tid >> 2;                 // 0..63
        const int m0 = (tid & 3) * 32;
        const float* sp = st + k * 129 + m0;
        #pragma unroll
        for (int mm = 0; mm < 16; mm++) {
            uint32_t h, l;
            split2(sp[2 * mm], sp[2 * mm + 1], h, l);
            *(uint32_t*)&Ahi[k * LDA_COL + m0 + 2 * mm] = h;
            *(uint32_t*)&Alo[k * LDA_COL + m0 + 2 * mm] = l;
        }
    }
}

// ---------------- GEMM1: g_Bu[l][b][s] = u(b,:,l) . Bm(s,:)  (bf16x3 WMMA) ----
__global__ __launch_bounds__(256, 2) void gemm1_wmma(const float* __restrict__ u) {
    extern __shared__ char smem[];
    const int tid = threadIdx.x, wid = tid >> 5;
    const int l0 = blockIdx.x * 128, s0 = blockIdx.y * 64, b = blockIdx.z;
    const int wm = wid & 3, wn = wid >> 2;      // 4 x 2 warps, warp tile 32x32

    __nv_bfloat16* Ahi = (__nv_bfloat16*)(smem + OFF_AHI);
    __nv_bfloat16* Alo = (__nv_bfloat16*)(smem + OFF_ALO);

    wmma::fragment<wmma::accumulator, 16, 16, 16, float> acc[2][2];
    #pragma unroll
    for (int i = 0; i < 2; i++)
        #pragma unroll
        for (int j = 0; j < 2; j++) wmma::fill_fragment(acc[i][j], 0.f);

    for (int k0 = 0; k0 < DI; k0 += 64) {
        fill_A_from_u(smem, u, b, k0, l0, tid);
        __syncthreads();

        #pragma unroll
        for (int kk = 0; kk < 4; kk++) {
            wmma::fragment<wmma::matrix_a, 16, 16, 16, __nv_bfloat16, wmma::col_major> ah[2], al[2];
            wmma::fragment<wmma::matrix_b, 16, 16, 16, __nv_bfloat16, wmma::col_major> bh[2], bl[2];
            #pragma unroll
            for (int i = 0; i < 2; i++) {
                const __nv_bfloat16* ap = Ahi + (kk * 16) * LDA_COL + wm * 32 + i * 16;
                const __nv_bfloat16* lp = Alo + (kk * 16) * LDA_COL + wm * 32 + i * 16;
                wmma::load_matrix_sync(ah[i], ap, LDA_COL);
                wmma::load_matrix_sync(al[i], lp, LDA_COL);
            }
            #pragma unroll
            for (int j = 0; j < 2; j++) {
                size_t woff = (size_t)(s0 + wn * 32 + j * 16) * DI + k0 + kk * 16;
                wmma::load_matrix_sync(bh[j], g_whi + WB_OFF + woff, DI);
                wmma::load_matrix_sync(bl[j], g_wlo + WB_OFF + woff, DI);
            }
            #pragma unroll
            for (int i = 0; i < 2; i++)
                #pragma unroll
                for (int j = 0; j < 2; j++) {
                    wmma::mma_sync(acc[i][j], ah[i], bh[j], acc[i][j]);
                    wmma::mma_sync(acc[i][j], ah[i], bl[j], acc[i][j]);
                    wmma::mma_sync(acc[i][j], al[i], bh[j], acc[i][j]);
                }
        }
        __syncthreads();
    }

    // direct store: (m=l, n=s) -> g_Bu[(l)(b)(s)], row stride BZ*DS
    #pragma unroll
    for (int i = 0; i < 2; i++)
        #pragma unroll
        for (int j = 0; j < 2; j++) {
            float* out = g_Bu + (size_t)(l0 + wm * 32 + i * 16) * (BZ * DS)
                              + (size_t)b * DS + s0 + wn * 32 + j * 16;
            wmma::store_matrix_sync(out, acc[i][j], BZ * DS, wmma::mem_row_major);
        }
}

// ---------------- GEMM2: Y[b][o][l] = C.x + D.u  (bf16x3 WMMA) ----------------
__global__ __launch_bounds__(256, 2) void gemm2_wmma(const float* __restrict__ u,
                                                     float* __restrict__ Y) {
    extern __shared__ char smem[];
    const int tid = threadIdx.x, wid = tid >> 5;
    const int l0 = blockIdx.x * 128, o0 = blockIdx.y * 64, b = blockIdx.z;
    const int wm = wid & 3, wn = wid >> 2;

    __nv_bfloat16* Ahi = (__nv_bfloat16*)(smem + OFF_AHI);
    __nv_bfloat16* Alo = (__nv_bfloat16*)(smem + OFF_ALO);

    wmma::fragment<wmma::accumulator, 16, 16, 16, float> acc[2][2];
    #pragma unroll
    for (int i = 0; i < 2; i++)
        #pragma unroll
        for (int j = 0; j < 2; j++) wmma::fill_fragment(acc[i][j], 0.f);

    // ---- Phase 1: K over DS; A = x from g_Bu (s-contiguous) row-major [m=l][k=s] ----
    for (int ck = 0; ck < DS / 64; ck++) {
        __syncthreads();   // protect Ahi/Alo from previous iteration's fragment reads
        {
            const int m = tid >> 1;                 // 0..127
            const int kseg = (tid & 1) * 32;
            const float* xp = g_Bu + ((size_t)(l0 + m) * BZ + b) * DS + ck * 64 + kseg;
            #pragma unroll
            for (int q = 0; q < 16; q++) {
                uint32_t h, l;
                split2(xp[2 * q], xp[2 * q + 1], h, l);
                *(uint32_t*)&Ahi[m * LDA_ROW + kseg + 2 * q] = h;
                *(uint32_t*)&Alo[m * LDA_ROW + kseg + 2 * q] = l;
            }
        }
        __syncthreads();

        #pragma unroll
        for (int kk = 0; kk < 4; kk++) {
            wmma::fragment<wmma::matrix_a, 16, 16, 16, __nv_bfloat16, wmma::row_major> ah[2], al[2];
            wmma::fragment<wmma::matrix_b, 16, 16, 16, __nv_bfloat16, wmma::col_major> bh[2], bl[2];
            #pragma unroll
            for (int i = 0; i < 2; i++) {
                const __nv_bfloat16* ap = Ahi + (wm * 32 + i * 16) * LDA_ROW + kk * 16;
                const __nv_bfloat16* lp = Alo + (wm * 32 + i * 16) * LDA_ROW + kk * 16;
                wmma::load_matrix_sync(ah[i], ap, LDA_ROW);
                wmma::load_matrix_sync(al[i], lp, LDA_ROW);
            }
            #pragma unroll
            for (int j = 0; j < 2; j++) {
                size_t woff = (size_t)(o0 + wn * 32 + j * 16) * DS + ck * 64 + kk * 16;
                wmma::load_matrix_sync(bh[j], g_whi + WC_OFF + woff, DS);
                wmma::load_matrix_sync(bl[j], g_wlo + WC_OFF + woff, DS);
            }
            #pragma unroll
            for (int i = 0; i < 2; i++)
                #pragma unroll
                for (int j = 0; j < 2; j++) {
                    wmma::mma_sync(acc[i][j], ah[i], bh[j], acc[i][j]);
                    wmma::mma_sync(acc[i][j], ah[i], bl[j], acc[i][j]);
                    wmma::mma_sync(acc[i][j], al[i], bh[j], acc[i][j]);
                }
        }
    }

    // ---- Phase 2: K over DI; A = u (staged transpose), col-major ----
    for (int k0 = 0; k0 < DI; k0 += 64) {
        __syncthreads();
        fill_A_from_u(smem, u, b, k0, l0, tid);
        __syncthreads();

        #pragma unroll
        for (int kk = 0; kk < 4; kk++) {
            wmma::fragment<wmma::matrix_a, 16, 16, 16, __nv_bfloat16, wmma::col_major> ah[2], al[2];
            wmma::fragment<wmma::matrix_b, 16, 16, 16, __nv_bfloat16, wmma::col_major> bh[2], bl[2];
            #pragma unroll
            for (int i = 0; i < 2; i++) {
                const __nv_bfloat16* ap = Ahi + (kk * 16) * LDA_COL + wm * 32 + i * 16;
                const __nv_bfloat16* lp = Alo + (kk * 16) * LDA_COL + wm * 32 + i * 16;
                wmma::load_matrix_sync(ah[i], ap, LDA_COL);
                wmma::load_matrix_sync(al[i], lp, LDA_COL);
            }
            #pragma unroll
            for (int j = 0; j < 2; j++) {
                size_t woff = (size_t)(o0 + wn * 32 + j * 16) * DI + k0 + kk * 16;
                wmma::load_matrix_sync(bh[j], g_whi + WD_OFF + woff, DI);
                wmma::load_matrix_sync(bl[j], g_wlo + WD_OFF + woff, DI);
            }
            #pragma unroll
            for (int i = 0; i < 2; i++)
                #pragma unroll
                for (int j = 0; j < 2; j++) {
                    wmma::mma_sync(acc[i][j], ah[i], bh[j], acc[i][j]);
                    wmma::mma_sync(acc[i][j], ah[i], bl[j], acc[i][j]);
                    wmma::mma_sync(acc[i][j], al[i], bh[j], acc[i][j]);
                }
        }
    }

    // ---- epilogue: acc tile is (m=l, n=o); transpose via smem, write l-contiguous ----
    __syncthreads();
    float* stg = (float*)(smem + OFF_STG);   // [128][72]
    #pragma unroll
    for (int i = 0; i < 2; i++)
        #pragma unroll
        for (int j = 0; j < 2; j++) {
            float* sp = stg + (size_t)(wm * 32 + i * 16) * LDA_ROW + wn * 32 + j * 16;
            wmma::store_matrix_sync(sp, acc[i][j], LDA_ROW, wmma::mem_row_major);
        }
    __syncthreads();
    {
        const int o = tid >> 2;                 // 0..63
        const int lseg = (tid & 3) * 32;
        float* yp = Y + ((size_t)b * DO + o0 + o) * LL + l0 + lseg;
        const float* sp = stg + (size_t)lseg * LDA_ROW + o;
        #pragma unroll
        for (int q = 0; q < 8; q++) {
            float4 v = make_float4(sp[(q * 4 + 0) * LDA_ROW], sp[(q * 4 + 1) * LDA_ROW],
                                   sp[(q * 4 + 2) * LDA_ROW], sp[(q * 4 + 3) * LDA_ROW]);
            *(float4*)(yp + q * 4) = v;
        }
    }
}

// ---------------- scan (unchanged from passing R4 kernel) ----------------
__global__ __launch_bounds__(256) void scanA_kernel(const float* __restrict__ Aun) {
    const int t = blockIdx.x * 256 + threadIdx.x;
    const int lane = t & (LANES - 1);
    const int c = t >> 12;
    const int s = lane & (DS - 1);
    const float A = -softplus_f(Aun[s]);
    const float* g = g_Bu + (size_t)(c * CLEN) * LANES + lane;
    float x = 0.f;
    #pragma unroll 8
    for (int j = 0; j < CLEN; j++) x = fmaf(A, x, g[(size_t)j * LANES]);
    g_last[t] = x;
}

__global__ __launch_bounds__(256) void scanB_kernel(const float* __restrict__ Aun,
                                                    const float* __restrict__ h0) {
    const int lane = blockIdx.x * 256 + threadIdx.x;
    const int s = lane & (DS - 1);
    const float A = -softplus_f(Aun[s]);
    float Ap = A;
    #pragma unroll
    for (int i = 0; i < 7; i++) Ap *= Ap;
    float h = h0[s];
    #pragma unroll
    for (int c = 0; c < NCH; c++) {
        g_carry[c * LANES + lane] = h;
        h = fmaf(Ap, h, g_last[c * LANES + lane]);
    }
}

__global__ __launch_bounds__(256) void scanC_kernel(const float* __restrict__ Aun) {
    const int t = blockIdx.x * 256 + threadIdx.x;
    const int lane = t & (LANES - 1);
    const int c = t >> 12;
    const int s = lane & (DS - 1);
    const float A = -softplus_f(Aun[s]);
    float x = g_carry[t];
    float* g = g_Bu + (size_t)(c * CLEN) * LANES + lane;
    #pragma unroll 4
    for (int j = 0; j < CLEN; j++) {
        float v = g[(size_t)j * LANES];
        x = fmaf(A, x, v);
        g[(size_t)j * LANES] = x;
    }
}

// ---------------- launch ----------------
extern "C" void kernel_launch(void* const* d_in, const int* in_sizes, int n_in,
                              void* d_out, int out_size) {
    const float* u   = (const float*)d_in[0];
    const float* Aun = (const float*)d_in[1];
    const float* Bm  = (const float*)d_in[2];
    const float* Cm  = (const float*)d_in[3];
    const float* Dm  = (const float*)d_in[4];
    const float* h0  = (const float*)d_in[5];
    float* Y = (float*)d_out;

    cudaFuncSetAttribute(gemm1_wmma, cudaFuncAttributeMaxDynamicSharedMemorySize, SMEM_BYTES);
    cudaFuncSetAttribute(gemm2_wmma, cudaFuncAttributeMaxDynamicSharedMemorySize, SMEM_BYTES);

    prep_kernel<<<(WTOT + 255) / 256, 256>>>(Bm, Cm, Dm);

    dim3 g1(LL / 128, DS / 64, BZ);
    gemm1_wmma<<<g1, 256, SMEM_BYTES>>>(u);

    scanA_kernel<<<(NCH * LANES) / 256, 256>>>(Aun);
    scanB_kernel<<<LANES / 256, 256>>>(Aun, h0);
    scanC_kernel<<<(NCH * LANES) / 256, 256>>>(Aun);

    dim3 g2(LL / 128, DO / 64, BZ);
    gemm2_wmma<<<g2, 256, SMEM_BYTES>>>(u, Y);
}